// round 5
// baseline (speedup 1.0000x reference)
#include <cuda_runtime.h>
#include <math.h>

// Problem constants
#define NB   2
#define NN   50000
#define NE   800000
#define INPD 128
#define NKEY 64
#define NVAL 128
#define M_ROWS (NB * NN)   // 100000 flattened (b, n) rows
#define SCAN_BLK 1024
#define SCAN_NBLK ((NN + SCAN_BLK - 1) / SCAN_BLK)   // 49

// ---------------- scratch (device globals; no allocation allowed) ----------
__device__ float d_values[(size_t)M_ROWS * NVAL];  // [b][n][v]
__device__ float d_agg[(size_t)M_ROWS * NVAL];     // [b][n][v]
__device__ float d_ksum[M_ROWS];                   // [b][n]
__device__ float d_kwsum[INPD];
__device__ float d_kbsum;
__device__ int    d_cnt[NN];
__device__ int    d_cnt2[NN];
__device__ int    d_offs[NN + 1];
__device__ int    d_bsum[SCAN_NBLK];
__device__ int    d_bsumex[SCAN_NBLK];
__device__ float2 d_score[NE];   // CSR-ordered (score_b0, score_b1)
__device__ int    d_ecol[NE];    // CSR-ordered sender col

// ---------------- tf32 helpers ----------------
__device__ __forceinline__ unsigned cvt_tf32(float x) {
    unsigned r;
    asm("cvt.rna.tf32.f32 %0, %1;" : "=r"(r) : "f"(x));
    return r;
}
#define MMA_TF32(c, a0, a1, a2, a3, b0, b1) \
    asm("mma.sync.aligned.m16n8k8.row.col.f32.tf32.tf32.f32 " \
        "{%0,%1,%2,%3}, {%4,%5,%6,%7}, {%8,%9}, {%0,%1,%2,%3};" \
        : "+f"((c)[0]), "+f"((c)[1]), "+f"((c)[2]), "+f"((c)[3]) \
        : "r"(a0), "r"(a1), "r"(a2), "r"(a3), "r"(b0), "r"(b1))

#define AS_STRIDE 36
#define BS_STRIDE 132

// ---------------- prep: kw row-sums, kb sum ----------------
__global__ void prep_k(const float* __restrict__ k_w, const float* __restrict__ k_b) {
    int i = threadIdx.x;
    if (i < INPD) {
        float s = 0.f;
        #pragma unroll
        for (int j = 0; j < NKEY; j++) s += k_w[i * NKEY + j];
        d_kwsum[i] = s;
    }
    if (i == 0) {
        float b = 0.f;
        #pragma unroll
        for (int j = 0; j < NKEY; j++) b += k_b[j];
        d_kbsum = b;
    }
}

__global__ void zero_cnt_k() {
    int i = blockIdx.x * blockDim.x + threadIdx.x;
    if (i < NN) { d_cnt[i] = 0; d_cnt2[i] = 0; }
}

__global__ void hist_k(const int* __restrict__ rows) {
    int e = blockIdx.x * blockDim.x + threadIdx.x;
    if (e < NE) atomicAdd(&d_cnt[rows[e]], 1);
}

// ---------------- 3-phase parallel scan ----------------
__global__ __launch_bounds__(SCAN_BLK) void scan1_k() {
    __shared__ int wsum[32];
    int tid = threadIdx.x, lane = tid & 31, wid = tid >> 5;
    int i = blockIdx.x * SCAN_BLK + tid;
    int v = (i < NN) ? d_cnt[i] : 0;
    int x = v;
    #pragma unroll
    for (int d = 1; d < 32; d <<= 1) {
        int t = __shfl_up_sync(0xffffffffu, x, d);
        if (lane >= d) x += t;
    }
    if (lane == 31) wsum[wid] = x;
    __syncthreads();
    if (wid == 0) {
        int s = wsum[lane];
        #pragma unroll
        for (int d = 1; d < 32; d <<= 1) {
            int t = __shfl_up_sync(0xffffffffu, s, d);
            if (lane >= d) s += t;
        }
        wsum[lane] = s;
    }
    __syncthreads();
    int pre = (wid > 0) ? wsum[wid - 1] : 0;
    if (i < NN) d_offs[i] = pre + x - v;
    if (tid == SCAN_BLK - 1) d_bsum[blockIdx.x] = pre + x;
}

__global__ void scan2_k() {
    if (threadIdx.x == 0) {
        int acc = 0;
        #pragma unroll
        for (int b = 0; b < SCAN_NBLK; b++) {
            int t = d_bsum[b];
            d_bsumex[b] = acc;
            acc += t;
        }
        d_offs[NN] = acc;
    }
}

__global__ void scan3_k() {
    int i = blockIdx.x * blockDim.x + threadIdx.x;
    if (i < NN) d_offs[i] += d_bsumex[i >> 10];
}

// ---------------- ksum: d_ksum[row] = x[row] . kwsum + kbsum ---------------
__global__ __launch_bounds__(256) void ksum_k(const float* __restrict__ x) {
    int gw = (blockIdx.x * 256 + threadIdx.x) >> 5;
    int lane = threadIdx.x & 31;
    if (gw >= M_ROWS) return;
    float4 xv = *(const float4*)&x[(size_t)gw * INPD + lane * 4];
    float4 kw = *(const float4*)&d_kwsum[lane * 4];
    float s = xv.x * kw.x + xv.y * kw.y + xv.z * kw.z + xv.w * kw.w;
    #pragma unroll
    for (int off = 16; off; off >>= 1) s += __shfl_xor_sync(0xffffffffu, s, off);
    if (lane == 0) d_ksum[gw] = s + d_kbsum;
}

// scatter: CSR-order scores + cols (ksum must be ready)
__global__ void scatter_k(const int* __restrict__ rows, const int* __restrict__ cols_,
                          const float* __restrict__ conn) {
    int e = blockIdx.x * blockDim.x + threadIdx.x;
    if (e < NE) {
        int r = rows[e];
        int c = cols_[e];
        float cv = conn[e];
        int p = d_offs[r] + atomicAdd(&d_cnt2[r], 1);
        d_score[p] = make_float2(cv * d_ksum[c], cv * d_ksum[NN + c]);
        d_ecol[p] = c;
    }
}

// ---------------- tf32 GEMM core (shared by both GEMMs) --------------------
// Block: 256 thr / 8 warps, tile 128(M) x 128(N), K in 4 chunks of 32.
// Warp tile 64m x 32n: warp_m = (warp&1)*64, warp_n = (warp>>1)*32.
// 3xTF32 split for ~fp32 accuracy.
struct Frag {
    float c[16][4];   // [mt*4+nt][4]
};

__device__ __forceinline__ void gemm_tf32_mainloop(
    const float* __restrict__ A, const float* __restrict__ W,
    float* As, float* Bs, float (&c)[16][4], size_t row0)
{
    int tid = threadIdx.x;
    int lane = tid & 31;
    int g = lane >> 2, t = lane & 3;
    int warp = tid >> 5;
    int warp_m = (warp & 1) * 64;
    int warp_n = (warp >> 1) * 32;

    #pragma unroll
    for (int i = 0; i < 16; i++)
        #pragma unroll
        for (int j = 0; j < 4; j++) c[i][j] = 0.f;

    for (int kc = 0; kc < 128; kc += 32) {
        // stage W: 32 rows x 128 cols -> Bs[k][n], stride 132
        #pragma unroll
        for (int q = 0; q < 4; q++) {
            int l = tid + q * 256;
            int k = l >> 5, n = (l & 31) * 4;
            *(float4*)&Bs[k * BS_STRIDE + n] = *(const float4*)&W[(size_t)(kc + k) * NVAL + n];
        }
        // stage A: 128 rows x 32 k -> As[m][k], stride 36
        #pragma unroll
        for (int q = 0; q < 4; q++) {
            int l = tid + q * 256;
            int r = l >> 3, kq = (l & 7) * 4;
            size_t row = row0 + r;
            if (row >= M_ROWS) row = M_ROWS - 1;
            *(float4*)&As[r * AS_STRIDE + kq] = *(const float4*)&A[row * 128 + kc + kq];
        }
        __syncthreads();

        #pragma unroll
        for (int kk = 0; kk < 4; kk++) {
            int k0 = kk * 8;
            // B fragments + split (once per ntile)
            unsigned bhi[4][2], blo[4][2];
            #pragma unroll
            for (int nt = 0; nt < 4; nt++) {
                int n0 = warp_n + nt * 8;
                float b0 = Bs[(k0 + t) * BS_STRIDE + n0 + g];
                float b1 = Bs[(k0 + t + 4) * BS_STRIDE + n0 + g];
                bhi[nt][0] = cvt_tf32(b0);
                bhi[nt][1] = cvt_tf32(b1);
                blo[nt][0] = cvt_tf32(b0 - __uint_as_float(bhi[nt][0]));
                blo[nt][1] = cvt_tf32(b1 - __uint_as_float(bhi[nt][1]));
            }
            #pragma unroll
            for (int mt = 0; mt < 4; mt++) {
                int m0 = warp_m + mt * 16;
                float a0 = As[(m0 + g) * AS_STRIDE + k0 + t];
                float a1 = As[(m0 + g + 8) * AS_STRIDE + k0 + t];
                float a2 = As[(m0 + g) * AS_STRIDE + k0 + t + 4];
                float a3 = As[(m0 + g + 8) * AS_STRIDE + k0 + t + 4];
                unsigned ah0 = cvt_tf32(a0), ah1 = cvt_tf32(a1);
                unsigned ah2 = cvt_tf32(a2), ah3 = cvt_tf32(a3);
                unsigned al0 = cvt_tf32(a0 - __uint_as_float(ah0));
                unsigned al1 = cvt_tf32(a1 - __uint_as_float(ah1));
                unsigned al2 = cvt_tf32(a2 - __uint_as_float(ah2));
                unsigned al3 = cvt_tf32(a3 - __uint_as_float(ah3));
                #pragma unroll
                for (int nt = 0; nt < 4; nt++) {
                    float* cc = c[mt * 4 + nt];
                    MMA_TF32(cc, ah0, ah1, ah2, ah3, bhi[nt][0], bhi[nt][1]);
                    MMA_TF32(cc, ah0, ah1, ah2, ah3, blo[nt][0], blo[nt][1]);
                    MMA_TF32(cc, al0, al1, al2, al3, bhi[nt][0], bhi[nt][1]);
                }
            }
        }
        __syncthreads();
    }
}

// ---------------- GEMM A: values = x @ v_w + v_b ---------------------------
__global__ __launch_bounds__(256) void gemm_values_k(
    const float* __restrict__ x, const float* __restrict__ v_w,
    const float* __restrict__ v_b)
{
    __shared__ __align__(16) float As[128 * AS_STRIDE];
    __shared__ __align__(16) float Bs[32 * BS_STRIDE];
    float c[16][4];
    size_t row0 = (size_t)blockIdx.x * 128;
    gemm_tf32_mainloop(x, v_w, As, Bs, c, row0);

    int tid = threadIdx.x;
    int lane = tid & 31;
    int g = lane >> 2, t = lane & 3;
    int warp = tid >> 5;
    int warp_m = (warp & 1) * 64;
    int warp_n = (warp >> 1) * 32;

    #pragma unroll
    for (int mt = 0; mt < 4; mt++) {
        size_t ra = row0 + warp_m + mt * 16 + g;
        size_t rb = ra + 8;
        #pragma unroll
        for (int nt = 0; nt < 4; nt++) {
            int n0 = warp_n + nt * 8 + 2 * t;
            float2 bv = *(const float2*)&v_b[n0];
            float* cc = c[mt * 4 + nt];
            if (ra < M_ROWS)
                *(float2*)&d_values[ra * NVAL + n0] = make_float2(cc[0] + bv.x, cc[1] + bv.y);
            if (rb < M_ROWS)
                *(float2*)&d_values[rb * NVAL + n0] = make_float2(cc[2] + bv.x, cc[3] + bv.y);
        }
    }
}

// ---------------- Edge kernel: per-row softmax + weighted gather-sum -------
__global__ __launch_bounds__(256) void edge_k() {
    int gw = (blockIdx.x * 256 + threadIdx.x) >> 5;
    int lane = threadIdx.x & 31;
    if (gw >= NN) return;
    int n = gw;
    int beg = d_offs[n], end = d_offs[n + 1];
    float* a0 = &d_agg[(size_t)n * NVAL];
    float* a1 = &d_agg[((size_t)NN + n) * NVAL];
    if (beg == end) {
        float4 z = {0.f, 0.f, 0.f, 0.f};
        *(float4*)&a0[lane * 4] = z;
        *(float4*)&a1[lane * 4] = z;
        return;
    }

    float m0 = -1e30f, dd0 = 0.f, m1 = -1e30f, dd1 = 0.f;
    for (int i = beg + lane; i < end; i += 32) {
        float2 s = d_score[i];
        if (s.x > m0) { dd0 = dd0 * __expf(m0 - s.x) + 1.f; m0 = s.x; }
        else          { dd0 += __expf(s.x - m0); }
        if (s.y > m1) { dd1 = dd1 * __expf(m1 - s.y) + 1.f; m1 = s.y; }
        else          { dd1 += __expf(s.y - m1); }
    }
    #pragma unroll
    for (int off = 16; off; off >>= 1) {
        float om = __shfl_xor_sync(0xffffffffu, m0, off);
        float od = __shfl_xor_sync(0xffffffffu, dd0, off);
        float nm = fmaxf(m0, om);
        dd0 = dd0 * __expf(m0 - nm) + od * __expf(om - nm);
        m0 = nm;
        om = __shfl_xor_sync(0xffffffffu, m1, off);
        od = __shfl_xor_sync(0xffffffffu, dd1, off);
        nm = fmaxf(m1, om);
        dd1 = dd1 * __expf(m1 - nm) + od * __expf(om - nm);
        m1 = nm;
    }
    float inv0 = 1.f / dd0;
    float inv1 = 1.f / dd1;

    float4 acc0 = {0.f, 0.f, 0.f, 0.f};
    float4 acc1 = {0.f, 0.f, 0.f, 0.f};
    const float* v0b = d_values;
    const float* v1b = d_values + (size_t)NN * NVAL;
    for (int base = beg; base < end; base += 32) {
        int i = base + lane;
        float w0 = 0.f, w1 = 0.f;
        int c = 0;
        if (i < end) {
            float2 s = d_score[i];
            c = d_ecol[i];
            w0 = __expf(s.x - m0) * inv0;
            w1 = __expf(s.y - m1) * inv1;
        }
        int cnt = min(32, end - base);
        for (int j = 0; j < cnt; j++) {
            float wj0 = __shfl_sync(0xffffffffu, w0, j);
            float wj1 = __shfl_sync(0xffffffffu, w1, j);
            int   cj  = __shfl_sync(0xffffffffu, c, j);
            float4 v0 = *(const float4*)&v0b[(size_t)cj * NVAL + lane * 4];
            float4 v1 = *(const float4*)&v1b[(size_t)cj * NVAL + lane * 4];
            acc0.x += wj0 * v0.x; acc0.y += wj0 * v0.y;
            acc0.z += wj0 * v0.z; acc0.w += wj0 * v0.w;
            acc1.x += wj1 * v1.x; acc1.y += wj1 * v1.y;
            acc1.z += wj1 * v1.z; acc1.w += wj1 * v1.w;
        }
    }
    *(float4*)&a0[lane * 4] = acc0;
    *(float4*)&a1[lane * 4] = acc1;
}

// ---------------- GEMM C: h = agg @ out_w + out_b ; silu; layernorm --------
__global__ __launch_bounds__(256) void gemm_out_k(
    const float* __restrict__ ow, const float* __restrict__ ob,
    const float* __restrict__ lng, const float* __restrict__ lnb,
    float* __restrict__ out)
{
    __shared__ __align__(16) float As[128 * AS_STRIDE];
    __shared__ __align__(16) float Bs[32 * BS_STRIDE];
    __shared__ float S1[4][128];
    __shared__ float S2[4][128];
    float c[16][4];
    size_t row0 = (size_t)blockIdx.x * 128;
    gemm_tf32_mainloop(d_agg, ow, As, Bs, c, row0);

    int tid = threadIdx.x;
    int lane = tid & 31;
    int g = lane >> 2, t = lane & 3;
    int warp = tid >> 5;
    int warp_m = (warp & 1) * 64;
    int warp_n = (warp >> 1) * 32;
    int wn = warp >> 1;

    // bias + silu in registers; per-row partial sums
    #pragma unroll
    for (int mt = 0; mt < 4; mt++) {
        float sa1 = 0.f, sa2 = 0.f, sb1 = 0.f, sb2 = 0.f;
        #pragma unroll
        for (int nt = 0; nt < 4; nt++) {
            int n0 = warp_n + nt * 8 + 2 * t;
            float2 bv = *(const float2*)&ob[n0];
            float* cc = c[mt * 4 + nt];
            float h0 = cc[0] + bv.x, h1 = cc[1] + bv.y;
            float h2 = cc[2] + bv.x, h3 = cc[3] + bv.y;
            h0 = h0 / (1.f + __expf(-h0)); h1 = h1 / (1.f + __expf(-h1));
            h2 = h2 / (1.f + __expf(-h2)); h3 = h3 / (1.f + __expf(-h3));
            cc[0] = h0; cc[1] = h1; cc[2] = h2; cc[3] = h3;
            sa1 += h0 + h1; sa2 += h0 * h0 + h1 * h1;
            sb1 += h2 + h3; sb2 += h2 * h2 + h3 * h3;
        }
        // reduce over the quad (t = 0..3 share the same rows)
        #pragma unroll
        for (int off = 1; off < 4; off <<= 1) {
            sa1 += __shfl_xor_sync(0xffffffffu, sa1, off);
            sa2 += __shfl_xor_sync(0xffffffffu, sa2, off);
            sb1 += __shfl_xor_sync(0xffffffffu, sb1, off);
            sb2 += __shfl_xor_sync(0xffffffffu, sb2, off);
        }
        if (t == 0) {
            int ra = warp_m + mt * 16 + g;
            S1[wn][ra] = sa1; S2[wn][ra] = sa2;
            S1[wn][ra + 8] = sb1; S2[wn][ra + 8] = sb2;
        }
    }
    __syncthreads();

    #pragma unroll
    for (int mt = 0; mt < 4; mt++) {
        int ral = warp_m + mt * 16 + g;
        float s1a = S1[0][ral] + S1[1][ral] + S1[2][ral] + S1[3][ral];
        float s2a = S2[0][ral] + S2[1][ral] + S2[2][ral] + S2[3][ral];
        float s1b = S1[0][ral + 8] + S1[1][ral + 8] + S1[2][ral + 8] + S1[3][ral + 8];
        float s2b = S2[0][ral + 8] + S2[1][ral + 8] + S2[2][ral + 8] + S2[3][ral + 8];
        float mua = s1a * (1.f / NVAL);
        float vara = s2a * (1.f / NVAL) - mua * mua;
        float rsa = rsqrtf(vara + 1e-5f);
        float mub = s1b * (1.f / NVAL);
        float varb = s2b * (1.f / NVAL) - mub * mub;
        float rsb = rsqrtf(varb + 1e-5f);
        size_t ra = row0 + ral;
        size_t rb = ra + 8;
        #pragma unroll
        for (int nt = 0; nt < 4; nt++) {
            int n0 = warp_n + nt * 8 + 2 * t;
            float2 gg = *(const float2*)&lng[n0];
            float2 bb = *(const float2*)&lnb[n0];
            float* cc = c[mt * 4 + nt];
            if (ra < M_ROWS) {
                float2 o;
                o.x = (cc[0] - mua) * rsa * gg.x + bb.x;
                o.y = (cc[1] - mua) * rsa * gg.y + bb.y;
                *(float2*)&out[ra * NVAL + n0] = o;
            }
            if (rb < M_ROWS) {
                float2 o;
                o.x = (cc[2] - mub) * rsb * gg.x + bb.x;
                o.y = (cc[3] - mub) * rsb * gg.y + bb.y;
                *(float2*)&out[rb * NVAL + n0] = o;
            }
        }
    }
}

// ---------------- launch ---------------------------------------------------
extern "C" void kernel_launch(void* const* d_in, const int* in_sizes, int n_in,
                              void* d_out, int out_size) {
    const float* x      = (const float*)d_in[0];
    const float* conn   = (const float*)d_in[1];
    const float* k_w    = (const float*)d_in[2];
    const float* k_b    = (const float*)d_in[3];
    const float* v_w    = (const float*)d_in[4];
    const float* v_b    = (const float*)d_in[5];
    const float* out_w  = (const float*)d_in[6];
    const float* out_b  = (const float*)d_in[7];
    const float* ln_g   = (const float*)d_in[8];
    const float* ln_b   = (const float*)d_in[9];
    const int*   rows   = (const int*)d_in[10];
    const int*   cols   = (const int*)d_in[11];
    float* out = (float*)d_out;

    prep_k<<<1, 128>>>(k_w, k_b);
    zero_cnt_k<<<(NN + 255) / 256, 256>>>();
    hist_k<<<(NE + 255) / 256, 256>>>(rows);
    scan1_k<<<SCAN_NBLK, SCAN_BLK>>>();
    scan2_k<<<1, 32>>>();
    scan3_k<<<(NN + 255) / 256, 256>>>();
    ksum_k<<<(M_ROWS + 7) / 8, 256>>>(x);
    scatter_k<<<(NE + 255) / 256, 256>>>(rows, cols, conn);
    gemm_values_k<<<(M_ROWS + 127) / 128, 256>>>(x, v_w, v_b);
    edge_k<<<(NN + 7) / 8, 256>>>();
    gemm_out_k<<<(M_ROWS + 127) / 128, 256>>>(out_w, out_b, ln_g, ln_b, out);
}

// round 6
// speedup vs baseline: 1.1360x; 1.1360x over previous
#include <cuda_runtime.h>
#include <cuda_fp16.h>
#include <math.h>

// Problem constants
#define NB   2
#define NN   50000
#define NE   800000
#define INPD 128
#define NKEY 64
#define NVAL 128
#define M_ROWS (NB * NN)   // 100000 flattened (b, n) rows
#define SCAN_BLK 1024
#define SCAN_NBLK ((NN + SCAN_BLK - 1) / SCAN_BLK)   // 49

// ---------------- scratch (device globals; no allocation allowed) ----------
__device__ __half d_values[(size_t)M_ROWS * NVAL]; // [b][n][v]  (fp16 storage)
__device__ float d_agg[(size_t)M_ROWS * NVAL];     // [b][n][v]
__device__ float d_ksum[M_ROWS];                   // [b][n]
__device__ float d_kwsum[INPD];
__device__ float d_kbsum;
__device__ int    d_cnt[NN];
__device__ int    d_cnt2[NN];
__device__ int    d_offs[NN + 1];
__device__ int    d_bsum[SCAN_NBLK];
__device__ int    d_bsumex[SCAN_NBLK];
__device__ float2 d_score[NE];   // CSR-ordered (score_b0, score_b1)
__device__ int    d_ecol[NE];    // CSR-ordered sender col

// ---------------- prep: kw row-sums, kb sum ----------------
__global__ void prep_k(const float* __restrict__ k_w, const float* __restrict__ k_b) {
    int i = threadIdx.x;
    if (i < INPD) {
        float s = 0.f;
        #pragma unroll
        for (int j = 0; j < NKEY; j++) s += k_w[i * NKEY + j];
        d_kwsum[i] = s;
    }
    if (i == 0) {
        float b = 0.f;
        #pragma unroll
        for (int j = 0; j < NKEY; j++) b += k_b[j];
        d_kbsum = b;
    }
}

__global__ void zero_cnt_k() {
    int i = blockIdx.x * blockDim.x + threadIdx.x;
    if (i < NN) { d_cnt[i] = 0; d_cnt2[i] = 0; }
}

__global__ void hist_k(const int* __restrict__ rows) {
    int e = blockIdx.x * blockDim.x + threadIdx.x;
    if (e < NE) atomicAdd(&d_cnt[rows[e]], 1);
}

// ---------------- 3-phase parallel scan ----------------
__global__ __launch_bounds__(SCAN_BLK) void scan1_k() {
    __shared__ int wsum[32];
    int tid = threadIdx.x, lane = tid & 31, wid = tid >> 5;
    int i = blockIdx.x * SCAN_BLK + tid;
    int v = (i < NN) ? d_cnt[i] : 0;
    int x = v;
    #pragma unroll
    for (int d = 1; d < 32; d <<= 1) {
        int t = __shfl_up_sync(0xffffffffu, x, d);
        if (lane >= d) x += t;
    }
    if (lane == 31) wsum[wid] = x;
    __syncthreads();
    if (wid == 0) {
        int s = wsum[lane];
        #pragma unroll
        for (int d = 1; d < 32; d <<= 1) {
            int t = __shfl_up_sync(0xffffffffu, s, d);
            if (lane >= d) s += t;
        }
        wsum[lane] = s;
    }
    __syncthreads();
    int pre = (wid > 0) ? wsum[wid - 1] : 0;
    if (i < NN) d_offs[i] = pre + x - v;           // block-local exclusive
    if (tid == SCAN_BLK - 1) d_bsum[blockIdx.x] = pre + x;
}

__global__ void scan2_k() {
    if (threadIdx.x == 0) {
        int acc = 0;
        #pragma unroll
        for (int b = 0; b < SCAN_NBLK; b++) {
            int t = d_bsum[b];
            d_bsumex[b] = acc;
            acc += t;
        }
        d_offs[NN] = acc;
    }
}

__global__ void scan3_k() {
    int i = blockIdx.x * blockDim.x + threadIdx.x;
    if (i < NN) d_offs[i] += d_bsumex[i >> 10];
}

// scatter: CSR-order scores + cols (ksum must be ready)
__global__ void scatter_k(const int* __restrict__ rows, const int* __restrict__ cols_,
                          const float* __restrict__ conn) {
    int e = blockIdx.x * blockDim.x + threadIdx.x;
    if (e < NE) {
        int r = rows[e];
        int c = cols_[e];
        float cv = conn[e];
        int p = d_offs[r] + atomicAdd(&d_cnt2[r], 1);
        d_score[p] = make_float2(cv * d_ksum[c], cv * d_ksum[NN + c]);
        d_ecol[p] = c;
    }
}

// ---------------- GEMM A: values = x @ v_w + v_b ; ksum fused --------------
// Tile: 64 rows x 128 cols; 256 threads; warp tr owns rows tr*8..tr*8+7,
// lane owns cols lane*4..lane*4+3. fp32 math, fp16 store.
__global__ __launch_bounds__(256) void gemm_values_k(
    const float* __restrict__ x, const float* __restrict__ v_w,
    const float* __restrict__ v_b)
{
    __shared__ __align__(16) float Ws[32][NVAL];   // 16KB
    __shared__ __align__(16) float As[64][32];     // 8KB
    __shared__ float Ks[32];
    int tid = threadIdx.x;
    int tr = tid >> 5, lane = tid & 31;
    size_t row0 = (size_t)blockIdx.x * 64;

    float acc[8][4];
    #pragma unroll
    for (int r = 0; r < 8; r++)
        #pragma unroll
        for (int c = 0; c < 4; c++) acc[r][c] = 0.f;
    float ksp[8];
    #pragma unroll
    for (int r = 0; r < 8; r++) ksp[r] = 0.f;

    for (int kc = 0; kc < INPD; kc += 32) {
        // Ws: 32x128 = 1024 float4, 256 threads x 4
        #pragma unroll
        for (int q = 0; q < 4; q++) {
            int l = tid + q * 256;            // float4 index
            int k = l >> 5, c = (l & 31) * 4;
            *(float4*)&Ws[k][c] = *(const float4*)&v_w[(size_t)(kc + k) * NVAL + c];
        }
        // As: 64x32 = 512 float4, 256 threads x 2
        #pragma unroll
        for (int q = 0; q < 2; q++) {
            int l = tid + q * 256;
            int r = l >> 3, kq = (l & 7) * 4;
            size_t row = row0 + r;
            if (row >= M_ROWS) row = M_ROWS - 1;
            *(float4*)&As[r][kq] = *(const float4*)&x[row * INPD + kc + kq];
        }
        if (tid < 32) Ks[tid] = d_kwsum[kc + tid];
        __syncthreads();

        #pragma unroll
        for (int k4 = 0; k4 < 8; k4++) {
            float4 a4[8];
            #pragma unroll
            for (int rr = 0; rr < 8; rr++)
                a4[rr] = *(const float4*)&As[tr * 8 + rr][k4 * 4];
            #pragma unroll
            for (int kk = 0; kk < 4; kk++) {
                float4 w = *(const float4*)&Ws[k4 * 4 + kk][lane * 4];
                #pragma unroll
                for (int rr = 0; rr < 8; rr++) {
                    float av = (kk == 0) ? a4[rr].x : (kk == 1) ? a4[rr].y
                             : (kk == 2) ? a4[rr].z : a4[rr].w;
                    acc[rr][0] += av * w.x; acc[rr][1] += av * w.y;
                    acc[rr][2] += av * w.z; acc[rr][3] += av * w.w;
                }
            }
        }
        #pragma unroll
        for (int rr = 0; rr < 8; rr++)
            ksp[rr] += As[tr * 8 + rr][lane] * Ks[lane];
        __syncthreads();
    }

    float4 vb = *(const float4*)&v_b[lane * 4];
    #pragma unroll
    for (int rr = 0; rr < 8; rr++) {
        size_t row = row0 + tr * 8 + rr;
        if (row < M_ROWS) {
            __half2 h0 = __floats2half2_rn(acc[rr][0] + vb.x, acc[rr][1] + vb.y);
            __half2 h1 = __floats2half2_rn(acc[rr][2] + vb.z, acc[rr][3] + vb.w);
            uint2 st;
            st.x = *(unsigned*)&h0;
            st.y = *(unsigned*)&h1;
            *(uint2*)&d_values[row * NVAL + lane * 4] = st;
        }
    }
    #pragma unroll
    for (int rr = 0; rr < 8; rr++) {
        float s = ksp[rr];
        #pragma unroll
        for (int off = 16; off; off >>= 1) s += __shfl_xor_sync(0xffffffffu, s, off);
        size_t row = row0 + tr * 8 + rr;
        if (lane == 0 && row < M_ROWS) d_ksum[row] = s + d_kbsum;
    }
}

// ---------------- Edge kernel: per-row softmax + weighted gather-sum -------
__global__ __launch_bounds__(256) void edge_k() {
    int gw = (blockIdx.x * 256 + threadIdx.x) >> 5;
    int lane = threadIdx.x & 31;
    if (gw >= NN) return;
    int n = gw;
    int beg = d_offs[n], end = d_offs[n + 1];
    float* a0 = &d_agg[(size_t)n * NVAL];
    float* a1 = &d_agg[((size_t)NN + n) * NVAL];
    if (beg == end) {
        float4 z = {0.f, 0.f, 0.f, 0.f};
        *(float4*)&a0[lane * 4] = z;
        *(float4*)&a1[lane * 4] = z;
        return;
    }

    // pass 1: per-lane online softmax stats for both batches (coalesced float2)
    float m0 = -1e30f, dd0 = 0.f, m1 = -1e30f, dd1 = 0.f;
    for (int i = beg + lane; i < end; i += 32) {
        float2 s = d_score[i];
        if (s.x > m0) { dd0 = dd0 * __expf(m0 - s.x) + 1.f; m0 = s.x; }
        else          { dd0 += __expf(s.x - m0); }
        if (s.y > m1) { dd1 = dd1 * __expf(m1 - s.y) + 1.f; m1 = s.y; }
        else          { dd1 += __expf(s.y - m1); }
    }
    #pragma unroll
    for (int off = 16; off; off >>= 1) {
        float om = __shfl_xor_sync(0xffffffffu, m0, off);
        float od = __shfl_xor_sync(0xffffffffu, dd0, off);
        float nm = fmaxf(m0, om);
        dd0 = dd0 * __expf(m0 - nm) + od * __expf(om - nm);
        m0 = nm;
        om = __shfl_xor_sync(0xffffffffu, m1, off);
        od = __shfl_xor_sync(0xffffffffu, dd1, off);
        nm = fmaxf(m1, om);
        dd1 = dd1 * __expf(m1 - nm) + od * __expf(om - nm);
        m1 = nm;
    }
    float inv0 = 1.f / dd0;
    float inv1 = 1.f / dd1;

    // pass 2: weighted accumulate of fp16 values rows (256B / warp / batch)
    float4 acc0 = {0.f, 0.f, 0.f, 0.f};
    float4 acc1 = {0.f, 0.f, 0.f, 0.f};
    const __half* v0b = d_values;
    const __half* v1b = d_values + (size_t)NN * NVAL;
    for (int base = beg; base < end; base += 32) {
        int i = base + lane;
        float w0 = 0.f, w1 = 0.f;
        int c = 0;
        if (i < end) {
            float2 s = d_score[i];
            c = d_ecol[i];
            w0 = __expf(s.x - m0) * inv0;
            w1 = __expf(s.y - m1) * inv1;
        }
        int cnt = min(32, end - base);
        for (int j = 0; j < cnt; j++) {
            float wj0 = __shfl_sync(0xffffffffu, w0, j);
            float wj1 = __shfl_sync(0xffffffffu, w1, j);
            int   cj  = __shfl_sync(0xffffffffu, c, j);
            uint2 p0 = *(const uint2*)&v0b[(size_t)cj * NVAL + lane * 4];
            uint2 p1 = *(const uint2*)&v1b[(size_t)cj * NVAL + lane * 4];
            float2 v0a = __half22float2(*(__half2*)&p0.x);
            float2 v0c = __half22float2(*(__half2*)&p0.y);
            float2 v1a = __half22float2(*(__half2*)&p1.x);
            float2 v1c = __half22float2(*(__half2*)&p1.y);
            acc0.x += wj0 * v0a.x; acc0.y += wj0 * v0a.y;
            acc0.z += wj0 * v0c.x; acc0.w += wj0 * v0c.y;
            acc1.x += wj1 * v1a.x; acc1.y += wj1 * v1a.y;
            acc1.z += wj1 * v1c.x; acc1.w += wj1 * v1c.y;
        }
    }
    *(float4*)&a0[lane * 4] = acc0;
    *(float4*)&a1[lane * 4] = acc1;
}

// ---------------- GEMM C: h = agg @ out_w + out_b ; silu; layernorm --------
__global__ __launch_bounds__(256) void gemm_out_k(
    const float* __restrict__ ow, const float* __restrict__ ob,
    const float* __restrict__ lng, const float* __restrict__ lnb,
    float* __restrict__ out)
{
    __shared__ __align__(16) float Ws[32][NVAL];
    __shared__ __align__(16) float As[64][32];
    int tid = threadIdx.x;
    int tr = tid >> 5, lane = tid & 31;
    size_t row0 = (size_t)blockIdx.x * 64;

    float acc[8][4];
    #pragma unroll
    for (int r = 0; r < 8; r++)
        #pragma unroll
        for (int c = 0; c < 4; c++) acc[r][c] = 0.f;

    for (int kc = 0; kc < NVAL; kc += 32) {
        #pragma unroll
        for (int q = 0; q < 4; q++) {
            int l = tid + q * 256;
            int k = l >> 5, c = (l & 31) * 4;
            *(float4*)&Ws[k][c] = *(const float4*)&ow[(size_t)(kc + k) * NVAL + c];
        }
        #pragma unroll
        for (int q = 0; q < 2; q++) {
            int l = tid + q * 256;
            int r = l >> 3, kq = (l & 7) * 4;
            size_t row = row0 + r;
            if (row >= M_ROWS) row = M_ROWS - 1;
            *(float4*)&As[r][kq] = *(const float4*)&d_agg[row * NVAL + kc + kq];
        }
        __syncthreads();
        #pragma unroll
        for (int k4 = 0; k4 < 8; k4++) {
            float4 a4[8];
            #pragma unroll
            for (int rr = 0; rr < 8; rr++)
                a4[rr] = *(const float4*)&As[tr * 8 + rr][k4 * 4];
            #pragma unroll
            for (int kk = 0; kk < 4; kk++) {
                float4 w = *(const float4*)&Ws[k4 * 4 + kk][lane * 4];
                #pragma unroll
                for (int rr = 0; rr < 8; rr++) {
                    float av = (kk == 0) ? a4[rr].x : (kk == 1) ? a4[rr].y
                             : (kk == 2) ? a4[rr].z : a4[rr].w;
                    acc[rr][0] += av * w.x; acc[rr][1] += av * w.y;
                    acc[rr][2] += av * w.z; acc[rr][3] += av * w.w;
                }
            }
        }
        __syncthreads();
    }

    // silu + layernorm, all in registers (each warp owns complete rows)
    float4 b4 = *(const float4*)&ob[lane * 4];
    float4 g4 = *(const float4*)&lng[lane * 4];
    float4 bb4 = *(const float4*)&lnb[lane * 4];
    #pragma unroll
    for (int rr = 0; rr < 8; rr++) {
        float h0 = acc[rr][0] + b4.x, h1 = acc[rr][1] + b4.y;
        float h2 = acc[rr][2] + b4.z, h3 = acc[rr][3] + b4.w;
        h0 = h0 / (1.f + __expf(-h0)); h1 = h1 / (1.f + __expf(-h1));
        h2 = h2 / (1.f + __expf(-h2)); h3 = h3 / (1.f + __expf(-h3));
        float s1 = h0 + h1 + h2 + h3;
        float s2 = h0 * h0 + h1 * h1 + h2 * h2 + h3 * h3;
        #pragma unroll
        for (int off = 16; off; off >>= 1) {
            s1 += __shfl_xor_sync(0xffffffffu, s1, off);
            s2 += __shfl_xor_sync(0xffffffffu, s2, off);
        }
        float mu = s1 * (1.f / NVAL);
        float var = s2 * (1.f / NVAL) - mu * mu;
        float rs = rsqrtf(var + 1e-5f);
        size_t row = row0 + tr * 8 + rr;
        if (row < M_ROWS) {
            float4 o;
            o.x = (h0 - mu) * rs * g4.x + bb4.x;
            o.y = (h1 - mu) * rs * g4.y + bb4.y;
            o.z = (h2 - mu) * rs * g4.z + bb4.z;
            o.w = (h3 - mu) * rs * g4.w + bb4.w;
            *(float4*)&out[row * NVAL + lane * 4] = o;
        }
    }
}

// ---------------- launch ---------------------------------------------------
extern "C" void kernel_launch(void* const* d_in, const int* in_sizes, int n_in,
                              void* d_out, int out_size) {
    const float* x      = (const float*)d_in[0];
    const float* conn   = (const float*)d_in[1];
    const float* k_w    = (const float*)d_in[2];
    const float* k_b    = (const float*)d_in[3];
    const float* v_w    = (const float*)d_in[4];
    const float* v_b    = (const float*)d_in[5];
    const float* out_w  = (const float*)d_in[6];
    const float* out_b  = (const float*)d_in[7];
    const float* ln_g   = (const float*)d_in[8];
    const float* ln_b   = (const float*)d_in[9];
    const int*   rows   = (const int*)d_in[10];
    const int*   cols   = (const int*)d_in[11];
    float* out = (float*)d_out;

    prep_k<<<1, 128>>>(k_w, k_b);
    zero_cnt_k<<<(NN + 255) / 256, 256>>>();
    hist_k<<<(NE + 255) / 256, 256>>>(rows);
    scan1_k<<<SCAN_NBLK, SCAN_BLK>>>();
    scan2_k<<<1, 32>>>();
    scan3_k<<<(NN + 255) / 256, 256>>>();
    gemm_values_k<<<(M_ROWS + 63) / 64, 256>>>(x, v_w, v_b);
    scatter_k<<<(NE + 255) / 256, 256>>>(rows, cols, conn);
    edge_k<<<(NN + 7) / 8, 256>>>();
    gemm_out_k<<<(M_ROWS + 63) / 64, 256>>>(out_w, out_b, ln_g, ln_b, out);
}

// round 7
// speedup vs baseline: 1.5653x; 1.3779x over previous
#include <cuda_runtime.h>
#include <cuda_fp16.h>
#include <math.h>

// Problem constants
#define NB   2
#define NN   50000
#define NE   800000
#define INPD 128
#define NKEY 64
#define NVAL 128
#define M_ROWS (NB * NN)   // 100000 flattened (b, n) rows
#define SCAN_BLK 1024
#define SCAN_NBLK ((NN + SCAN_BLK - 1) / SCAN_BLK)   // 49

// ---------------- scratch (device globals; no allocation allowed) ----------
__device__ __half d_values[(size_t)M_ROWS * NVAL]; // [b][n][v]  (fp16 storage)
__device__ float d_agg[(size_t)M_ROWS * NVAL];     // [b][n][v]
__device__ float d_ksum[M_ROWS];                   // [b][n]
__device__ float d_kwsum[INPD];
__device__ float d_kbsum;
__device__ int    d_cnt[NN];
__device__ int    d_cnt2[NN];
__device__ int    d_offs[NN + 1];
__device__ int    d_bsum[SCAN_NBLK];
__device__ int    d_bsumex[SCAN_NBLK];
__device__ float2 d_score[NE];   // CSR-ordered (score_b0, score_b1)
__device__ int    d_ecol[NE];    // CSR-ordered sender col

// ---------------- tf32 helpers ----------------
__device__ __forceinline__ float tf32r(float x) {
    unsigned r;
    asm("cvt.rna.tf32.f32 %0, %1;" : "=r"(r) : "f"(x));
    return __uint_as_float(r);
}
#define MMA_TF32(c, a0, a1, a2, a3, b0, b1) \
    asm("mma.sync.aligned.m16n8k8.row.col.f32.tf32.tf32.f32 " \
        "{%0,%1,%2,%3}, {%4,%5,%6,%7}, {%8,%9}, {%0,%1,%2,%3};" \
        : "+f"((c)[0]), "+f"((c)[1]), "+f"((c)[2]), "+f"((c)[3]) \
        : "r"(a0), "r"(a1), "r"(a2), "r"(a3), "r"(b0), "r"(b1))

#define AS_STRIDE 36
#define BS_STRIDE 132

// ---------------- prep: kw row-sums, kb sum ----------------
__global__ void prep_k(const float* __restrict__ k_w, const float* __restrict__ k_b) {
    int i = threadIdx.x;
    if (i < INPD) {
        float s = 0.f;
        #pragma unroll
        for (int j = 0; j < NKEY; j++) s += k_w[i * NKEY + j];
        d_kwsum[i] = s;
    }
    if (i == 0) {
        float b = 0.f;
        #pragma unroll
        for (int j = 0; j < NKEY; j++) b += k_b[j];
        d_kbsum = b;
    }
}

__global__ void zero_cnt_k() {
    int i = blockIdx.x * blockDim.x + threadIdx.x;
    if (i < NN) { d_cnt[i] = 0; d_cnt2[i] = 0; }
}

__global__ void hist_k(const int* __restrict__ rows) {
    int e = blockIdx.x * blockDim.x + threadIdx.x;
    if (e < NE) atomicAdd(&d_cnt[rows[e]], 1);
}

// ---------------- 3-phase parallel scan ----------------
__global__ __launch_bounds__(SCAN_BLK) void scan1_k() {
    __shared__ int wsum[32];
    int tid = threadIdx.x, lane = tid & 31, wid = tid >> 5;
    int i = blockIdx.x * SCAN_BLK + tid;
    int v = (i < NN) ? d_cnt[i] : 0;
    int x = v;
    #pragma unroll
    for (int d = 1; d < 32; d <<= 1) {
        int t = __shfl_up_sync(0xffffffffu, x, d);
        if (lane >= d) x += t;
    }
    if (lane == 31) wsum[wid] = x;
    __syncthreads();
    if (wid == 0) {
        int s = wsum[lane];
        #pragma unroll
        for (int d = 1; d < 32; d <<= 1) {
            int t = __shfl_up_sync(0xffffffffu, s, d);
            if (lane >= d) s += t;
        }
        wsum[lane] = s;
    }
    __syncthreads();
    int pre = (wid > 0) ? wsum[wid - 1] : 0;
    if (i < NN) d_offs[i] = pre + x - v;
    if (tid == SCAN_BLK - 1) d_bsum[blockIdx.x] = pre + x;
}

__global__ void scan2_k() {
    if (threadIdx.x == 0) {
        int acc = 0;
        #pragma unroll
        for (int b = 0; b < SCAN_NBLK; b++) {
            int t = d_bsum[b];
            d_bsumex[b] = acc;
            acc += t;
        }
        d_offs[NN] = acc;
    }
}

__global__ void scan3_k() {
    int i = blockIdx.x * blockDim.x + threadIdx.x;
    if (i < NN) d_offs[i] += d_bsumex[i >> 10];
}

// ---------------- ksum: d_ksum[row] = x[row] . kwsum + kbsum ---------------
__global__ __launch_bounds__(256) void ksum_k(const float* __restrict__ x) {
    int gw = (blockIdx.x * 256 + threadIdx.x) >> 5;
    int lane = threadIdx.x & 31;
    if (gw >= M_ROWS) return;
    float4 xv = *(const float4*)&x[(size_t)gw * INPD + lane * 4];
    float4 kw = *(const float4*)&d_kwsum[lane * 4];
    float s = xv.x * kw.x + xv.y * kw.y + xv.z * kw.z + xv.w * kw.w;
    #pragma unroll
    for (int off = 16; off; off >>= 1) s += __shfl_xor_sync(0xffffffffu, s, off);
    if (lane == 0) d_ksum[gw] = s + d_kbsum;
}

// scatter: CSR-order scores + cols (ksum must be ready)
__global__ void scatter_k(const int* __restrict__ rows, const int* __restrict__ cols_,
                          const float* __restrict__ conn) {
    int e = blockIdx.x * blockDim.x + threadIdx.x;
    if (e < NE) {
        int r = rows[e];
        int c = cols_[e];
        float cv = conn[e];
        int p = d_offs[r] + atomicAdd(&d_cnt2[r], 1);
        d_score[p] = make_float2(cv * d_ksum[c], cv * d_ksum[NN + c]);
        d_ecol[p] = c;
    }
}

// ---------------- tf32 GEMM core (single-pass; rounding done at staging) ---
// Block: 256 thr / 8 warps, tile 128(M) x 128(N), K in 4 chunks of 32.
// Warp tile 64m x 32n: warp_m = (warp&1)*64, warp_n = (warp>>1)*32.
__device__ __forceinline__ void gemm_tf32_mainloop(
    const float* __restrict__ A, const float* __restrict__ W,
    float* As, float* Bs, float (&c)[16][4], size_t row0)
{
    int tid = threadIdx.x;
    int lane = tid & 31;
    int g = lane >> 2, t = lane & 3;
    int warp = tid >> 5;
    int warp_m = (warp & 1) * 64;
    int warp_n = (warp >> 1) * 32;

    #pragma unroll
    for (int i = 0; i < 16; i++)
        #pragma unroll
        for (int j = 0; j < 4; j++) c[i][j] = 0.f;

    for (int kc = 0; kc < 128; kc += 32) {
        // stage W: 32 rows x 128 cols -> Bs[k][n], tf32-rounded at store
        #pragma unroll
        for (int q = 0; q < 4; q++) {
            int l = tid + q * 256;
            int k = l >> 5, n = (l & 31) * 4;
            float4 w = *(const float4*)&W[(size_t)(kc + k) * NVAL + n];
            w.x = tf32r(w.x); w.y = tf32r(w.y); w.z = tf32r(w.z); w.w = tf32r(w.w);
            *(float4*)&Bs[k * BS_STRIDE + n] = w;
        }
        // stage A: 128 rows x 32 k -> As[m][k], tf32-rounded at store
        #pragma unroll
        for (int q = 0; q < 4; q++) {
            int l = tid + q * 256;
            int r = l >> 3, kq = (l & 7) * 4;
            size_t row = row0 + r;
            if (row >= M_ROWS) row = M_ROWS - 1;
            float4 a = *(const float4*)&A[row * 128 + kc + kq];
            a.x = tf32r(a.x); a.y = tf32r(a.y); a.z = tf32r(a.z); a.w = tf32r(a.w);
            *(float4*)&As[r * AS_STRIDE + kq] = a;
        }
        __syncthreads();

        #pragma unroll
        for (int kk = 0; kk < 4; kk++) {
            int k0 = kk * 8;
            unsigned b0[4], b1[4];
            #pragma unroll
            for (int nt = 0; nt < 4; nt++) {
                int n0 = warp_n + nt * 8;
                b0[nt] = __float_as_uint(Bs[(k0 + t) * BS_STRIDE + n0 + g]);
                b1[nt] = __float_as_uint(Bs[(k0 + t + 4) * BS_STRIDE + n0 + g]);
            }
            #pragma unroll
            for (int mt = 0; mt < 4; mt++) {
                int m0 = warp_m + mt * 16;
                unsigned a0 = __float_as_uint(As[(m0 + g) * AS_STRIDE + k0 + t]);
                unsigned a1 = __float_as_uint(As[(m0 + g + 8) * AS_STRIDE + k0 + t]);
                unsigned a2 = __float_as_uint(As[(m0 + g) * AS_STRIDE + k0 + t + 4]);
                unsigned a3 = __float_as_uint(As[(m0 + g + 8) * AS_STRIDE + k0 + t + 4]);
                #pragma unroll
                for (int nt = 0; nt < 4; nt++) {
                    MMA_TF32(c[mt * 4 + nt], a0, a1, a2, a3, b0[nt], b1[nt]);
                }
            }
        }
        __syncthreads();
    }
}

// ---------------- GEMM A: values = x @ v_w + v_b (fp16 store) --------------
__global__ __launch_bounds__(256) void gemm_values_k(
    const float* __restrict__ x, const float* __restrict__ v_w,
    const float* __restrict__ v_b)
{
    __shared__ __align__(16) float As[128 * AS_STRIDE];
    __shared__ __align__(16) float Bs[32 * BS_STRIDE];
    float c[16][4];
    size_t row0 = (size_t)blockIdx.x * 128;
    gemm_tf32_mainloop(x, v_w, As, Bs, c, row0);

    int tid = threadIdx.x;
    int lane = tid & 31;
    int g = lane >> 2, t = lane & 3;
    int warp = tid >> 5;
    int warp_m = (warp & 1) * 64;
    int warp_n = (warp >> 1) * 32;

    #pragma unroll
    for (int mt = 0; mt < 4; mt++) {
        size_t ra = row0 + warp_m + mt * 16 + g;
        size_t rb = ra + 8;
        #pragma unroll
        for (int nt = 0; nt < 4; nt++) {
            int n0 = warp_n + nt * 8 + 2 * t;
            float2 bv = *(const float2*)&v_b[n0];
            float* cc = c[mt * 4 + nt];
            if (ra < M_ROWS) {
                __half2 h = __floats2half2_rn(cc[0] + bv.x, cc[1] + bv.y);
                *(unsigned*)&d_values[ra * NVAL + n0] = *(unsigned*)&h;
            }
            if (rb < M_ROWS) {
                __half2 h = __floats2half2_rn(cc[2] + bv.x, cc[3] + bv.y);
                *(unsigned*)&d_values[rb * NVAL + n0] = *(unsigned*)&h;
            }
        }
    }
}

// ---------------- Edge kernel: per-row softmax + weighted gather-sum -------
__global__ __launch_bounds__(256) void edge_k() {
    int gw = (blockIdx.x * 256 + threadIdx.x) >> 5;
    int lane = threadIdx.x & 31;
    if (gw >= NN) return;
    int n = gw;
    int beg = d_offs[n], end = d_offs[n + 1];
    float* a0 = &d_agg[(size_t)n * NVAL];
    float* a1 = &d_agg[((size_t)NN + n) * NVAL];
    if (beg == end) {
        float4 z = {0.f, 0.f, 0.f, 0.f};
        *(float4*)&a0[lane * 4] = z;
        *(float4*)&a1[lane * 4] = z;
        return;
    }

    float m0 = -1e30f, dd0 = 0.f, m1 = -1e30f, dd1 = 0.f;
    for (int i = beg + lane; i < end; i += 32) {
        float2 s = d_score[i];
        if (s.x > m0) { dd0 = dd0 * __expf(m0 - s.x) + 1.f; m0 = s.x; }
        else          { dd0 += __expf(s.x - m0); }
        if (s.y > m1) { dd1 = dd1 * __expf(m1 - s.y) + 1.f; m1 = s.y; }
        else          { dd1 += __expf(s.y - m1); }
    }
    #pragma unroll
    for (int off = 16; off; off >>= 1) {
        float om = __shfl_xor_sync(0xffffffffu, m0, off);
        float od = __shfl_xor_sync(0xffffffffu, dd0, off);
        float nm = fmaxf(m0, om);
        dd0 = dd0 * __expf(m0 - nm) + od * __expf(om - nm);
        m0 = nm;
        om = __shfl_xor_sync(0xffffffffu, m1, off);
        od = __shfl_xor_sync(0xffffffffu, dd1, off);
        nm = fmaxf(m1, om);
        dd1 = dd1 * __expf(m1 - nm) + od * __expf(om - nm);
        m1 = nm;
    }
    float inv0 = 1.f / dd0;
    float inv1 = 1.f / dd1;

    float4 acc0 = {0.f, 0.f, 0.f, 0.f};
    float4 acc1 = {0.f, 0.f, 0.f, 0.f};
    const __half* v0b = d_values;
    const __half* v1b = d_values + (size_t)NN * NVAL;
    for (int base = beg; base < end; base += 32) {
        int i = base + lane;
        float w0 = 0.f, w1 = 0.f;
        int c = 0;
        if (i < end) {
            float2 s = d_score[i];
            c = d_ecol[i];
            w0 = __expf(s.x - m0) * inv0;
            w1 = __expf(s.y - m1) * inv1;
        }
        int cnt = min(32, end - base);
        for (int j = 0; j < cnt; j++) {
            float wj0 = __shfl_sync(0xffffffffu, w0, j);
            float wj1 = __shfl_sync(0xffffffffu, w1, j);
            int   cj  = __shfl_sync(0xffffffffu, c, j);
            uint2 p0 = *(const uint2*)&v0b[(size_t)cj * NVAL + lane * 4];
            uint2 p1 = *(const uint2*)&v1b[(size_t)cj * NVAL + lane * 4];
            float2 v0a = __half22float2(*(__half2*)&p0.x);
            float2 v0c = __half22float2(*(__half2*)&p0.y);
            float2 v1a = __half22float2(*(__half2*)&p1.x);
            float2 v1c = __half22float2(*(__half2*)&p1.y);
            acc0.x += wj0 * v0a.x; acc0.y += wj0 * v0a.y;
            acc0.z += wj0 * v0c.x; acc0.w += wj0 * v0c.y;
            acc1.x += wj1 * v1a.x; acc1.y += wj1 * v1a.y;
            acc1.z += wj1 * v1c.x; acc1.w += wj1 * v1c.y;
        }
    }
    *(float4*)&a0[lane * 4] = acc0;
    *(float4*)&a1[lane * 4] = acc1;
}

// ---------------- GEMM C: h = agg @ out_w + out_b ; silu; layernorm --------
__global__ __launch_bounds__(256) void gemm_out_k(
    const float* __restrict__ ow, const float* __restrict__ ob,
    const float* __restrict__ lng, const float* __restrict__ lnb,
    float* __restrict__ out)
{
    __shared__ __align__(16) float As[128 * AS_STRIDE];
    __shared__ __align__(16) float Bs[32 * BS_STRIDE];
    __shared__ float S1[4][128];
    __shared__ float S2[4][128];
    float c[16][4];
    size_t row0 = (size_t)blockIdx.x * 128;
    gemm_tf32_mainloop(d_agg, ow, As, Bs, c, row0);

    int tid = threadIdx.x;
    int lane = tid & 31;
    int g = lane >> 2, t = lane & 3;
    int warp = tid >> 5;
    int warp_m = (warp & 1) * 64;
    int warp_n = (warp >> 1) * 32;
    int wn = warp >> 1;

    // bias + silu in registers; per-row partial sums
    #pragma unroll
    for (int mt = 0; mt < 4; mt++) {
        float sa1 = 0.f, sa2 = 0.f, sb1 = 0.f, sb2 = 0.f;
        #pragma unroll
        for (int nt = 0; nt < 4; nt++) {
            int n0 = warp_n + nt * 8 + 2 * t;
            float2 bv = *(const float2*)&ob[n0];
            float* cc = c[mt * 4 + nt];
            float h0 = cc[0] + bv.x, h1 = cc[1] + bv.y;
            float h2 = cc[2] + bv.x, h3 = cc[3] + bv.y;
            h0 = h0 / (1.f + __expf(-h0)); h1 = h1 / (1.f + __expf(-h1));
            h2 = h2 / (1.f + __expf(-h2)); h3 = h3 / (1.f + __expf(-h3));
            cc[0] = h0; cc[1] = h1; cc[2] = h2; cc[3] = h3;
            sa1 += h0 + h1; sa2 += h0 * h0 + h1 * h1;
            sb1 += h2 + h3; sb2 += h2 * h2 + h3 * h3;
        }
        #pragma unroll
        for (int off = 1; off < 4; off <<= 1) {
            sa1 += __shfl_xor_sync(0xffffffffu, sa1, off);
            sa2 += __shfl_xor_sync(0xffffffffu, sa2, off);
            sb1 += __shfl_xor_sync(0xffffffffu, sb1, off);
            sb2 += __shfl_xor_sync(0xffffffffu, sb2, off);
        }
        if (t == 0) {
            int ra = warp_m + mt * 16 + g;
            S1[wn][ra] = sa1; S2[wn][ra] = sa2;
            S1[wn][ra + 8] = sb1; S2[wn][ra + 8] = sb2;
        }
    }
    __syncthreads();

    #pragma unroll
    for (int mt = 0; mt < 4; mt++) {
        int ral = warp_m + mt * 16 + g;
        float s1a = S1[0][ral] + S1[1][ral] + S1[2][ral] + S1[3][ral];
        float s2a = S2[0][ral] + S2[1][ral] + S2[2][ral] + S2[3][ral];
        float s1b = S1[0][ral + 8] + S1[1][ral + 8] + S1[2][ral + 8] + S1[3][ral + 8];
        float s2b = S2[0][ral + 8] + S2[1][ral + 8] + S2[2][ral + 8] + S2[3][ral + 8];
        float mua = s1a * (1.f / NVAL);
        float vara = s2a * (1.f / NVAL) - mua * mua;
        float rsa = rsqrtf(vara + 1e-5f);
        float mub = s1b * (1.f / NVAL);
        float varb = s2b * (1.f / NVAL) - mub * mub;
        float rsb = rsqrtf(varb + 1e-5f);
        size_t ra = row0 + ral;
        size_t rb = ra + 8;
        #pragma unroll
        for (int nt = 0; nt < 4; nt++) {
            int n0 = warp_n + nt * 8 + 2 * t;
            float2 gg = *(const float2*)&lng[n0];
            float2 bb = *(const float2*)&lnb[n0];
            float* cc = c[mt * 4 + nt];
            if (ra < M_ROWS) {
                float2 o;
                o.x = (cc[0] - mua) * rsa * gg.x + bb.x;
                o.y = (cc[1] - mua) * rsa * gg.y + bb.y;
                *(float2*)&out[ra * NVAL + n0] = o;
            }
            if (rb < M_ROWS) {
                float2 o;
                o.x = (cc[2] - mub) * rsb * gg.x + bb.x;
                o.y = (cc[3] - mub) * rsb * gg.y + bb.y;
                *(float2*)&out[rb * NVAL + n0] = o;
            }
        }
    }
}

// ---------------- launch ---------------------------------------------------
extern "C" void kernel_launch(void* const* d_in, const int* in_sizes, int n_in,
                              void* d_out, int out_size) {
    const float* x      = (const float*)d_in[0];
    const float* conn   = (const float*)d_in[1];
    const float* k_w    = (const float*)d_in[2];
    const float* k_b    = (const float*)d_in[3];
    const float* v_w    = (const float*)d_in[4];
    const float* v_b    = (const float*)d_in[5];
    const float* out_w  = (const float*)d_in[6];
    const float* out_b  = (const float*)d_in[7];
    const float* ln_g   = (const float*)d_in[8];
    const float* ln_b   = (const float*)d_in[9];
    const int*   rows   = (const int*)d_in[10];
    const int*   cols   = (const int*)d_in[11];
    float* out = (float*)d_out;

    prep_k<<<1, 128>>>(k_w, k_b);
    zero_cnt_k<<<(NN + 255) / 256, 256>>>();
    hist_k<<<(NE + 255) / 256, 256>>>(rows);
    scan1_k<<<SCAN_NBLK, SCAN_BLK>>>();
    scan2_k<<<1, 32>>>();
    scan3_k<<<(NN + 255) / 256, 256>>>();
    ksum_k<<<(M_ROWS + 7) / 8, 256>>>(x);
    scatter_k<<<(NE + 255) / 256, 256>>>(rows, cols, conn);
    gemm_values_k<<<(M_ROWS + 127) / 128, 256>>>(x, v_w, v_b);
    edge_k<<<(NN + 7) / 8, 256>>>();
    gemm_out_k<<<(M_ROWS + 127) / 128, 256>>>(out_w, out_b, ln_g, ln_b, out);
}